// round 2
// baseline (speedup 1.0000x reference)
#include <cuda_runtime.h>
#include <cstdio>

// Problem constants (fixed by the reference: B=2,H=16,N=4096,D=64,F=256)
#define BHp   32
#define Np    4096
#define Dp    64
#define Fp    256
#define CHUNK 64
#define GROUPS 16
#define ROWS_PER_GROUP (Np / GROUPS)           // 256
#define CHUNKS_PER_GROUP (ROWS_PER_GROUP / CHUNK) // 4

// Scratch: per-(b,h) kv [F,E] and ksum [F]
__device__ float g_kv[BHp * Fp * Dp];    // 2 MB
__device__ float g_ksum[BHp * Fp];       // 32 KB

__global__ void zero_scratch() {
    int i = blockIdx.x * blockDim.x + threadIdx.x;
    if (i < BHp * Fp * Dp) g_kv[i] = 0.0f;
    if (i < BHp * Fp)      g_ksum[i] = 0.0f;
}

// ---------------------------------------------------------------------------
// Kernel A: k-side. For each (pair, group): compute k' = softmax_kernel(k @ P)
// for 256 rows (4 chunks of 64), accumulate partial kv = k'^T v and ksum in
// registers, then atomically reduce into g_kv / g_ksum.
// smem: Ps[64*256] + xs[64*64] + vs[64*64] + kp[64*256] = 163840 B
// ---------------------------------------------------------------------------
__global__ __launch_bounds__(256, 1)
void kside_kernel(const float* __restrict__ K,
                  const float* __restrict__ V,
                  const float* __restrict__ P) {
    extern __shared__ float sm[];
    float* Ps = sm;                    // [64][256] projection matrix
    float* xs = Ps + Dp * Fp;          // [64][64]  k tile
    float* vs = xs + CHUNK * Dp;       // [64][64]  v tile
    float* kp = vs + CHUNK * Dp;       // [64][256] k' tile

    const int tid  = threadIdx.x;
    const int w    = tid >> 5;         // warp 0..7
    const int lane = tid & 31;
    const int pair = blockIdx.y;       // 0..31
    const int grp  = blockIdx.x;       // 0..15

    // load P (coalesced float4)
    for (int i = tid; i < Dp * Fp / 4; i += 256)
        ((float4*)Ps)[i] = ((const float4*)P)[i];

    // persistent accumulators: kv micro-tile acc[f=lane+32i][e=w*8+j], ksum part
    float acc[8][8];
    #pragma unroll
    for (int i = 0; i < 8; i++)
        #pragma unroll
        for (int j = 0; j < 8; j++) acc[i][j] = 0.0f;
    float ksp[8];
    #pragma unroll
    for (int j = 0; j < 8; j++) ksp[j] = 0.0f;

    __syncthreads();

    for (int c = 0; c < CHUNKS_PER_GROUP; c++) {
        const int row0 = grp * ROWS_PER_GROUP + c * CHUNK;
        const float* ksrc = K + ((size_t)pair * Np + row0) * Dp;
        const float* vsrc = V + ((size_t)pair * Np + row0) * Dp;
        for (int i = tid; i < CHUNK * Dp / 4; i += 256) {
            ((float4*)xs)[i] = ((const float4*)ksrc)[i];
            ((float4*)vs)[i] = ((const float4*)vsrc)[i];
        }
        __syncthreads();

        // ---- phase 1: projection. warp w owns rows w*8..w*8+7,
        //      lane owns features lane+32*j (j=0..7)
        float pr[8][8];
        #pragma unroll
        for (int i = 0; i < 8; i++)
            #pragma unroll
            for (int j = 0; j < 8; j++) pr[i][j] = 0.0f;

        for (int d = 0; d < Dp; d += 4) {
            float4 a4[8];
            #pragma unroll
            for (int i = 0; i < 8; i++)
                a4[i] = *(const float4*)&xs[(w * 8 + i) * Dp + d];
            #pragma unroll
            for (int dd = 0; dd < 4; dd++) {
                float bb[8];
                #pragma unroll
                for (int j = 0; j < 8; j++)
                    bb[j] = Ps[(d + dd) * Fp + lane + 32 * j];
                #pragma unroll
                for (int i = 0; i < 8; i++) {
                    const float av = (&a4[i].x)[dd];
                    #pragma unroll
                    for (int j = 0; j < 8; j++)
                        pr[i][j] = fmaf(av, bb[j], pr[i][j]);
                }
            }
        }

        // ---- softmax-kernel: row max (warp reduce), exp, scale 1/sqrt(256)
        #pragma unroll
        for (int i = 0; i < 8; i++) {
            float m = pr[i][0];
            #pragma unroll
            for (int j = 1; j < 8; j++) m = fmaxf(m, pr[i][j]);
            #pragma unroll
            for (int off = 16; off > 0; off >>= 1)
                m = fmaxf(m, __shfl_xor_sync(0xffffffffu, m, off));
            #pragma unroll
            for (int j = 0; j < 8; j++) {
                const float e = expf(pr[i][j] - m) * 0.0625f;
                kp[(w * 8 + i) * Fp + lane + 32 * j] = e;
                ksp[j] += e;
            }
        }
        __syncthreads();

        // ---- phase 2: kv += k'^T v over this chunk's 64 rows
        //      thread owns f = lane+32*i, e = w*8+j
        for (int r = 0; r < CHUNK; r++) {
            float a_[8];
            #pragma unroll
            for (int i = 0; i < 8; i++)
                a_[i] = kp[r * Fp + lane + 32 * i];
            const float4 b0 = *(const float4*)&vs[r * Dp + w * 8];
            const float4 b1 = *(const float4*)&vs[r * Dp + w * 8 + 4];
            const float b_[8] = {b0.x, b0.y, b0.z, b0.w, b1.x, b1.y, b1.z, b1.w};
            #pragma unroll
            for (int i = 0; i < 8; i++)
                #pragma unroll
                for (int j = 0; j < 8; j++)
                    acc[i][j] = fmaf(a_[i], b_[j], acc[i][j]);
        }
        __syncthreads();
    }

    // ---- reduce into global scratch
    float* kvg = g_kv + (size_t)pair * Fp * Dp;
    #pragma unroll
    for (int i = 0; i < 8; i++)
        #pragma unroll
        for (int j = 0; j < 8; j++)
            atomicAdd(&kvg[(lane + 32 * i) * Dp + w * 8 + j], acc[i][j]);
    float* ksg = g_ksum + (size_t)pair * Fp;
    #pragma unroll
    for (int j = 0; j < 8; j++)
        atomicAdd(&ksg[lane + 32 * j], ksp[j]);
}

// ---------------------------------------------------------------------------
// Kernel B: q-side. q' projection, then out = (q' kv) / (q' (ksum+1e-6)).
// smem: Ps[64*256] + xs[64*64] + qp[64*256] + kvs[256*64] + kss[256] = 214016 B
// ---------------------------------------------------------------------------
__global__ __launch_bounds__(256, 1)
void qside_kernel(const float* __restrict__ Q,
                  const float* __restrict__ P,
                  float* __restrict__ out) {
    extern __shared__ float sm[];
    float* Ps  = sm;                    // [64][256]
    float* xs  = Ps + Dp * Fp;          // [64][64]
    float* qp  = xs + CHUNK * Dp;       // [64][256]
    float* kvs = qp + CHUNK * Fp;       // [256][64]
    float* kss = kvs + Fp * Dp;         // [256]

    const int tid  = threadIdx.x;
    const int w    = tid >> 5;
    const int lane = tid & 31;
    const int pair = blockIdx.y;
    const int grp  = blockIdx.x;

    for (int i = tid; i < Dp * Fp / 4; i += 256)
        ((float4*)Ps)[i] = ((const float4*)P)[i];
    {
        const float* kvg = g_kv + (size_t)pair * Fp * Dp;
        for (int i = tid; i < Fp * Dp / 4; i += 256)
            ((float4*)kvs)[i] = ((const float4*)kvg)[i];
        kss[tid] = g_ksum[(size_t)pair * Fp + tid] + 1e-6f;
    }
    __syncthreads();

    for (int c = 0; c < CHUNKS_PER_GROUP; c++) {
        const int row0 = grp * ROWS_PER_GROUP + c * CHUNK;
        const float* qsrc = Q + ((size_t)pair * Np + row0) * Dp;
        for (int i = tid; i < CHUNK * Dp / 4; i += 256)
            ((float4*)xs)[i] = ((const float4*)qsrc)[i];
        __syncthreads();

        // ---- phase 1: projection (identical structure to kside)
        float pr[8][8];
        #pragma unroll
        for (int i = 0; i < 8; i++)
            #pragma unroll
            for (int j = 0; j < 8; j++) pr[i][j] = 0.0f;

        for (int d = 0; d < Dp; d += 4) {
            float4 a4[8];
            #pragma unroll
            for (int i = 0; i < 8; i++)
                a4[i] = *(const float4*)&xs[(w * 8 + i) * Dp + d];
            #pragma unroll
            for (int dd = 0; dd < 4; dd++) {
                float bb[8];
                #pragma unroll
                for (int j = 0; j < 8; j++)
                    bb[j] = Ps[(d + dd) * Fp + lane + 32 * j];
                #pragma unroll
                for (int i = 0; i < 8; i++) {
                    const float av = (&a4[i].x)[dd];
                    #pragma unroll
                    for (int j = 0; j < 8; j++)
                        pr[i][j] = fmaf(av, bb[j], pr[i][j]);
                }
            }
        }
        #pragma unroll
        for (int i = 0; i < 8; i++) {
            float m = pr[i][0];
            #pragma unroll
            for (int j = 1; j < 8; j++) m = fmaxf(m, pr[i][j]);
            #pragma unroll
            for (int off = 16; off > 0; off >>= 1)
                m = fmaxf(m, __shfl_xor_sync(0xffffffffu, m, off));
            #pragma unroll
            for (int j = 0; j < 8; j++)
                qp[(w * 8 + i) * Fp + lane + 32 * j] = expf(pr[i][j] - m) * 0.0625f;
        }
        __syncthreads();

        // ---- phase 2: out rows w*8+i, cols lane*2 .. lane*2+1; denom per row
        float oacc[8][2];
        float dn[8];
        #pragma unroll
        for (int i = 0; i < 8; i++) { oacc[i][0] = 0.0f; oacc[i][1] = 0.0f; dn[i] = 0.0f; }

        for (int f = 0; f < Fp; f++) {
            float a_[8];
            #pragma unroll
            for (int i = 0; i < 8; i++)
                a_[i] = qp[(w * 8 + i) * Fp + f];          // warp-uniform broadcast
            const float2 b = *(const float2*)&kvs[f * Dp + lane * 2];
            const float ks = kss[f];
            #pragma unroll
            for (int i = 0; i < 8; i++) {
                oacc[i][0] = fmaf(a_[i], b.x, oacc[i][0]);
                oacc[i][1] = fmaf(a_[i], b.y, oacc[i][1]);
                dn[i]      = fmaf(a_[i], ks,  dn[i]);
            }
        }

        float* od = out + ((size_t)pair * Np + row0) * Dp;
        #pragma unroll
        for (int i = 0; i < 8; i++) {
            const float inv = 1.0f / dn[i];
            float2 o;
            o.x = oacc[i][0] * inv;
            o.y = oacc[i][1] * inv;
            *(float2*)&od[(w * 8 + i) * Dp + lane * 2] = o;
        }
        __syncthreads();
    }
}

// ---------------------------------------------------------------------------
extern "C" void kernel_launch(void* const* d_in, const int* in_sizes, int n_in,
                              void* d_out, int out_size) {
    const float* q = (const float*)d_in[0];
    const float* k = (const float*)d_in[1];
    const float* v = (const float*)d_in[2];
    const float* p = (const float*)d_in[3];
    float* out = (float*)d_out;

    static_assert(sizeof(float4) == 16, "");

    const size_t smemA = (size_t)(Dp * Fp + CHUNK * Dp + CHUNK * Dp + CHUNK * Fp) * 4;           // 163840
    const size_t smemB = (size_t)(Dp * Fp + CHUNK * Dp + CHUNK * Fp + Fp * Dp + Fp) * 4;         // 214016

    cudaFuncSetAttribute(kside_kernel, cudaFuncAttributeMaxDynamicSharedMemorySize, (int)smemA);
    cudaFuncSetAttribute(qside_kernel, cudaFuncAttributeMaxDynamicSharedMemorySize, (int)smemB);

    // zero kv/ksum scratch (must happen every replay)
    {
        int total = BHp * Fp * Dp;   // covers ksum too (smaller)
        int blocks = (total + 255) / 256;
        zero_scratch<<<blocks, 256>>>();
    }

    dim3 grid(GROUPS, BHp);
    kside_kernel<<<grid, 256, smemA>>>(k, v, p);
    qside_kernel<<<grid, 256, smemB>>>(q, p, out);
}

// round 3
// speedup vs baseline: 2.1494x; 2.1494x over previous
#include <cuda_runtime.h>
#include <cuda_fp16.h>

// Problem constants: B=2,H=16,N=4096,D=64,F=256
#define BHp   32
#define Np    4096
#define Dp    64
#define Fp    256
#define CHUNK 64
#define GROUPS 16
#define ROWS_PER_GROUP 256
#define CHUNKS_PER_GROUP 4

// smem strides (in halves). 72 = 8 mod 64 -> conflict-free fragment loads.
#define XS_S  72
#define PT_S  72
#define VT_S  72
#define KPT_S 72
#define QP_S  264
#define KVT_S 264

__device__ float g_kv[BHp * Fp * Dp];    // per-(b,h) kv [F][E] fp32 scratch
__device__ float g_ksum[BHp * Fp];

__global__ void zero_scratch() {
    int i = blockIdx.x * blockDim.x + threadIdx.x;
    if (i < BHp * Fp * Dp) g_kv[i] = 0.0f;
    if (i < BHp * Fp)      g_ksum[i] = 0.0f;
}

// m16n8k16 f16 mma, f32 accumulate
__device__ __forceinline__ void mma16816(float* c,
                                         unsigned a0, unsigned a1, unsigned a2, unsigned a3,
                                         unsigned b0, unsigned b1) {
    asm volatile(
        "mma.sync.aligned.m16n8k16.row.col.f32.f16.f16.f32 "
        "{%0,%1,%2,%3},{%4,%5,%6,%7},{%8,%9},{%0,%1,%2,%3};"
        : "+f"(c[0]), "+f"(c[1]), "+f"(c[2]), "+f"(c[3])
        : "r"(a0), "r"(a1), "r"(a2), "r"(a3), "r"(b0), "r"(b1));
}

__device__ __forceinline__ unsigned lds_u32(const __half* p) {
    return *(const unsigned*)p;
}

// Load P^T (hi/lo f16 split) into smem: PT[f][d]
__device__ __forceinline__ void load_PT(const float* __restrict__ P,
                                        __half* PTh, __half* PTl, int tid) {
    for (int j = tid; j < Dp * Fp / 4; j += 256) {
        float4 v = ((const float4*)P)[j];
        int d = j / (Fp / 4);
        int f0 = (j % (Fp / 4)) * 4;
        #pragma unroll
        for (int u = 0; u < 4; u++) {
            float x = (&v.x)[u];
            __half hi = __float2half_rn(x);
            __half lo = __float2half_rn(x - __half2float(hi));
            PTh[(f0 + u) * PT_S + d] = hi;
            PTl[(f0 + u) * PT_S + d] = lo;
        }
    }
}

// Projection: pr[16][4] += X[m0..m0+15][0..63] @ P[0..63][fbase..fbase+127]
// via 3xF16 split mma. Warp-collective.
__device__ __forceinline__ void proj_mma(const __half* XSh, const __half* XSl,
                                         const __half* PTh, const __half* PTl,
                                         int m0, int fbase, int lane,
                                         float pr[16][4]) {
    #pragma unroll
    for (int t = 0; t < 16; t++) {
        pr[t][0] = 0.f; pr[t][1] = 0.f; pr[t][2] = 0.f; pr[t][3] = 0.f;
    }
    const int r  = lane >> 2;
    const int q2 = (lane & 3) * 2;
    #pragma unroll
    for (int k0 = 0; k0 < 64; k0 += 16) {
        const int ar0 = (m0 + r) * XS_S + k0 + q2;
        const int ar1 = (m0 + r + 8) * XS_S + k0 + q2;
        unsigned ah0 = lds_u32(XSh + ar0);
        unsigned ah1 = lds_u32(XSh + ar1);
        unsigned ah2 = lds_u32(XSh + ar0 + 8);
        unsigned ah3 = lds_u32(XSh + ar1 + 8);
        unsigned al0 = lds_u32(XSl + ar0);
        unsigned al1 = lds_u32(XSl + ar1);
        unsigned al2 = lds_u32(XSl + ar0 + 8);
        unsigned al3 = lds_u32(XSl + ar1 + 8);
        #pragma unroll
        for (int t = 0; t < 16; t++) {
            const int fb = (fbase + t * 8 + r) * PT_S + k0 + q2;
            unsigned bh0 = lds_u32(PTh + fb);
            unsigned bh1 = lds_u32(PTh + fb + 8);
            unsigned bl0 = lds_u32(PTl + fb);
            unsigned bl1 = lds_u32(PTl + fb + 8);
            mma16816(pr[t], ah0, ah1, ah2, ah3, bh0, bh1);
            mma16816(pr[t], ah0, ah1, ah2, ah3, bl0, bl1);
            mma16816(pr[t], al0, al1, al2, al3, bh0, bh1);
        }
    }
}

// Row-max partials -> RMAX[half][64]
__device__ __forceinline__ void rowmax_store(float pr[16][4], float* RMAX,
                                             int m0, int half, int lane) {
    const int r = lane >> 2;
    float mlo = -3.4e38f, mhi = -3.4e38f;
    #pragma unroll
    for (int t = 0; t < 16; t++) {
        mlo = fmaxf(mlo, fmaxf(pr[t][0], pr[t][1]));
        mhi = fmaxf(mhi, fmaxf(pr[t][2], pr[t][3]));
    }
    #pragma unroll
    for (int off = 1; off <= 2; off <<= 1) {
        mlo = fmaxf(mlo, __shfl_xor_sync(0xffffffffu, mlo, off));
        mhi = fmaxf(mhi, __shfl_xor_sync(0xffffffffu, mhi, off));
    }
    if ((lane & 3) == 0) {
        RMAX[half * 64 + m0 + r]     = mlo;
        RMAX[half * 64 + m0 + 8 + r] = mhi;
    }
}

// ---------------------------------------------------------------------------
// kside: k' projection + kv += k'^T v + ksum
// ---------------------------------------------------------------------------
__global__ __launch_bounds__(256, 1)
void kside_kernel(const float* __restrict__ K,
                  const float* __restrict__ V,
                  const float* __restrict__ P) {
    extern __shared__ char smraw[];
    __half* PTh = (__half*)smraw;                 // [256][72]
    __half* PTl = PTh + Fp * PT_S;
    __half* XSh = PTl + Fp * PT_S;                // [64][72]
    __half* XSl = XSh + CHUNK * XS_S;
    __half* VT  = XSl + CHUNK * XS_S;             // [64 e][72 r]
    __half* KPT = VT + CHUNK * VT_S;              // [256 f][72 r]
    float*  RMAX = (float*)(KPT + Fp * KPT_S);    // [2][64]

    const int tid  = threadIdx.x;
    const int w    = tid >> 5;
    const int lane = tid & 31;
    const int pair = blockIdx.y;
    const int grp  = blockIdx.x;
    const int r  = lane >> 2;
    const int q2 = (lane & 3) * 2;

    load_PT(P, PTh, PTl, tid);

    // persistent kv accumulators: warp owns f-tiles {2w,2w+1} x all 8 e-tiles
    float accv[2][8][4];
    #pragma unroll
    for (int mi = 0; mi < 2; mi++)
        #pragma unroll
        for (int t = 0; t < 8; t++)
            #pragma unroll
            for (int u = 0; u < 4; u++) accv[mi][t][u] = 0.f;
    float ksp = 0.f;

    for (int c = 0; c < CHUNKS_PER_GROUP; c++) {
        __syncthreads();   // prior chunk consumers done before overwriting tiles
        const int row0 = grp * ROWS_PER_GROUP + c * CHUNK;
        const float* ksrc = K + ((size_t)pair * Np + row0) * Dp;
        const float* vsrc = V + ((size_t)pair * Np + row0) * Dp;
        // x tile -> hi/lo halves; v tile -> transposed halves
        for (int j = tid; j < CHUNK * Dp / 4; j += 256) {
            float4 xv = ((const float4*)ksrc)[j];
            float4 vv = ((const float4*)vsrc)[j];
            int rr = j / (Dp / 4);
            int d0 = (j % (Dp / 4)) * 4;
            #pragma unroll
            for (int u = 0; u < 4; u++) {
                float x = (&xv.x)[u];
                __half hi = __float2half_rn(x);
                __half lo = __float2half_rn(x - __half2float(hi));
                XSh[rr * XS_S + d0 + u] = hi;
                XSl[rr * XS_S + d0 + u] = lo;
                VT[(d0 + u) * VT_S + rr] = __float2half_rn((&vv.x)[u]);
            }
        }
        __syncthreads();

        // projection
        const int m0 = (w >> 1) * 16;
        const int fbase = (w & 1) * 128;
        float pr[16][4];
        proj_mma(XSh, XSl, PTh, PTl, m0, fbase, lane, pr);
        rowmax_store(pr, RMAX, m0, (w & 1), lane);
        __syncthreads();

        // exp + transposed store into KPT[f][row]
        {
            const float Mlo = fmaxf(RMAX[m0 + r],     RMAX[64 + m0 + r]);
            const float Mhi = fmaxf(RMAX[m0 + 8 + r], RMAX[64 + m0 + 8 + r]);
            #pragma unroll
            for (int t = 0; t < 16; t++) {
                const int f = fbase + t * 8 + q2;
                KPT[f * KPT_S + m0 + r]           = __float2half_rn(__expf(pr[t][0] - Mlo) * 0.0625f);
                KPT[(f + 1) * KPT_S + m0 + r]     = __float2half_rn(__expf(pr[t][1] - Mlo) * 0.0625f);
                KPT[f * KPT_S + m0 + 8 + r]       = __float2half_rn(__expf(pr[t][2] - Mhi) * 0.0625f);
                KPT[(f + 1) * KPT_S + m0 + 8 + r] = __float2half_rn(__expf(pr[t][3] - Mhi) * 0.0625f);
            }
        }
        __syncthreads();

        // kv += k'^T v : D[f][e], A=KPT[f][r], B=VT[e][r]
        const int fw = w * 32;
        #pragma unroll
        for (int k0 = 0; k0 < 64; k0 += 16) {
            unsigned a[2][4];
            #pragma unroll
            for (int mi = 0; mi < 2; mi++) {
                const int base0 = (fw + mi * 16 + r) * KPT_S + k0 + q2;
                const int base1 = (fw + mi * 16 + 8 + r) * KPT_S + k0 + q2;
                a[mi][0] = lds_u32(KPT + base0);
                a[mi][1] = lds_u32(KPT + base1);
                a[mi][2] = lds_u32(KPT + base0 + 8);
                a[mi][3] = lds_u32(KPT + base1 + 8);
            }
            #pragma unroll
            for (int t = 0; t < 8; t++) {
                const int vb = (t * 8 + r) * VT_S + k0 + q2;
                unsigned b0 = lds_u32(VT + vb);
                unsigned b1 = lds_u32(VT + vb + 8);
                mma16816(accv[0][t], a[0][0], a[0][1], a[0][2], a[0][3], b0, b1);
                mma16816(accv[1][t], a[1][0], a[1][1], a[1][2], a[1][3], b0, b1);
            }
        }

        // ksum partial: thread tid owns feature tid
        {
            const __half2* rowp = (const __half2*)(KPT + tid * KPT_S);
            float sx = 0.f, sy = 0.f;
            #pragma unroll
            for (int j = 0; j < 32; j++) {
                float2 f2 = __half22float2(rowp[j]);
                sx += f2.x; sy += f2.y;
            }
            ksp += sx + sy;
        }
    }

    // reduce to global
    float* kvg = g_kv + (size_t)pair * Fp * Dp;
    #pragma unroll
    for (int mi = 0; mi < 2; mi++) {
        const int f0 = w * 32 + mi * 16 + r;
        #pragma unroll
        for (int t = 0; t < 8; t++) {
            const int e = t * 8 + q2;
            atomicAdd(&kvg[f0 * Dp + e],           accv[mi][t][0]);
            atomicAdd(&kvg[f0 * Dp + e + 1],       accv[mi][t][1]);
            atomicAdd(&kvg[(f0 + 8) * Dp + e],     accv[mi][t][2]);
            atomicAdd(&kvg[(f0 + 8) * Dp + e + 1], accv[mi][t][3]);
        }
    }
    atomicAdd(&g_ksum[(size_t)pair * Fp + tid], ksp);
}

// ---------------------------------------------------------------------------
// qside: q' projection + out = (q' kv) / (q' (ksum+1e-6))
// ---------------------------------------------------------------------------
__global__ __launch_bounds__(256, 1)
void qside_kernel(const float* __restrict__ Q,
                  const float* __restrict__ P,
                  float* __restrict__ out) {
    extern __shared__ char smraw[];
    __half* PTh = (__half*)smraw;                  // [256][72]
    __half* PTl = PTh + Fp * PT_S;
    __half* XSh = PTl + Fp * PT_S;                 // [64][72]
    __half* XSl = XSh + CHUNK * XS_S;
    __half* QP  = XSl + CHUNK * XS_S;              // [64 row][264 f]
    __half* KVTh = QP + CHUNK * QP_S;              // [64 e][264 f]
    __half* KVTl = KVTh + CHUNK * KVT_S;
    float*  KSS  = (float*)(KVTl + CHUNK * KVT_S); // [256]
    float*  RMAX = KSS + Fp;                       // [2][64]
    float*  DNI  = RMAX + 128;                     // [64]

    const int tid  = threadIdx.x;
    const int w    = tid >> 5;
    const int lane = tid & 31;
    const int pair = blockIdx.y;
    const int grp  = blockIdx.x;
    const int r  = lane >> 2;
    const int q2 = (lane & 3) * 2;

    load_PT(P, PTh, PTl, tid);

    // kv -> transposed hi/lo halves; ksum -> fp32
    {
        const float* kvg = g_kv + (size_t)pair * Fp * Dp;
        for (int j = tid; j < Fp * Dp / 4; j += 256) {
            float4 v = ((const float4*)kvg)[j];
            int f = j / (Dp / 4);
            int e0 = (j % (Dp / 4)) * 4;
            #pragma unroll
            for (int u = 0; u < 4; u++) {
                float x = (&v.x)[u];
                __half hi = __float2half_rn(x);
                __half lo = __float2half_rn(x - __half2float(hi));
                KVTh[(e0 + u) * KVT_S + f] = hi;
                KVTl[(e0 + u) * KVT_S + f] = lo;
            }
        }
        if (tid < Fp) KSS[tid] = g_ksum[(size_t)pair * Fp + tid] + 1e-6f;
    }

    for (int c = 0; c < CHUNKS_PER_GROUP; c++) {
        __syncthreads();
        const int row0 = grp * ROWS_PER_GROUP + c * CHUNK;
        const float* qsrc = Q + ((size_t)pair * Np + row0) * Dp;
        for (int j = tid; j < CHUNK * Dp / 4; j += 256) {
            float4 xv = ((const float4*)qsrc)[j];
            int rr = j / (Dp / 4);
            int d0 = (j % (Dp / 4)) * 4;
            #pragma unroll
            for (int u = 0; u < 4; u++) {
                float x = (&xv.x)[u];
                __half hi = __float2half_rn(x);
                __half lo = __float2half_rn(x - __half2float(hi));
                XSh[rr * XS_S + d0 + u] = hi;
                XSl[rr * XS_S + d0 + u] = lo;
            }
        }
        __syncthreads();

        const int m0 = (w >> 1) * 16;
        const int fbase = (w & 1) * 128;
        float pr[16][4];
        proj_mma(XSh, XSl, PTh, PTl, m0, fbase, lane, pr);
        rowmax_store(pr, RMAX, m0, (w & 1), lane);
        __syncthreads();

        // exp + row-major store QP[row][f] (half2)
        {
            const float Mlo = fmaxf(RMAX[m0 + r],     RMAX[64 + m0 + r]);
            const float Mhi = fmaxf(RMAX[m0 + 8 + r], RMAX[64 + m0 + 8 + r]);
            #pragma unroll
            for (int t = 0; t < 16; t++) {
                const int f = fbase + t * 8 + q2;
                __half2 lo2 = __floats2half2_rn(__expf(pr[t][0] - Mlo) * 0.0625f,
                                                __expf(pr[t][1] - Mlo) * 0.0625f);
                __half2 hi2 = __floats2half2_rn(__expf(pr[t][2] - Mhi) * 0.0625f,
                                                __expf(pr[t][3] - Mhi) * 0.0625f);
                *(__half2*)(QP + (m0 + r) * QP_S + f)     = lo2;
                *(__half2*)(QP + (m0 + 8 + r) * QP_S + f) = hi2;
            }
        }
        __syncthreads();

        // denom: warp w owns rows w*8..w*8+7
        {
            #pragma unroll
            for (int rr = 0; rr < 8; rr++) {
                const int row = w * 8 + rr;
                float s = 0.f;
                #pragma unroll
                for (int j = 0; j < 8; j++) {
                    const int f = lane + 32 * j;
                    s = fmaf(__half2float(QP[row * QP_S + f]), KSS[f], s);
                }
                #pragma unroll
                for (int off = 16; off > 0; off >>= 1)
                    s += __shfl_xor_sync(0xffffffffu, s, off);
                if (lane == 0) DNI[row] = 1.0f / s;
            }
        }

        // out mma: D[row][e], A=QP[row][f], B=KVT[e][f] (hi + lo)
        const int om0 = (w >> 1) * 16;
        const int nb  = (w & 1) * 32;
        float oc[4][4];
        #pragma unroll
        for (int t = 0; t < 4; t++)
            #pragma unroll
            for (int u = 0; u < 4; u++) oc[t][u] = 0.f;

        #pragma unroll
        for (int k0 = 0; k0 < 256; k0 += 16) {
            const int ab0 = (om0 + r) * QP_S + k0 + q2;
            const int ab1 = (om0 + 8 + r) * QP_S + k0 + q2;
            unsigned a0 = lds_u32(QP + ab0);
            unsigned a1 = lds_u32(QP + ab1);
            unsigned a2 = lds_u32(QP + ab0 + 8);
            unsigned a3 = lds_u32(QP + ab1 + 8);
            #pragma unroll
            for (int t = 0; t < 4; t++) {
                const int bb = (nb + t * 8 + r) * KVT_S + k0 + q2;
                unsigned bh0 = lds_u32(KVTh + bb);
                unsigned bh1 = lds_u32(KVTh + bb + 8);
                unsigned bl0 = lds_u32(KVTl + bb);
                unsigned bl1 = lds_u32(KVTl + bb + 8);
                mma16816(oc[t], a0, a1, a2, a3, bh0, bh1);
                mma16816(oc[t], a0, a1, a2, a3, bl0, bl1);
            }
        }
        __syncthreads();   // DNI visible to all

        float* od = out + ((size_t)pair * Np + row0) * Dp;
        const float ilo = DNI[om0 + r];
        const float ihi = DNI[om0 + 8 + r];
        #pragma unroll
        for (int t = 0; t < 4; t++) {
            const int e = nb + t * 8 + q2;
            float2 v0 = make_float2(oc[t][0] * ilo, oc[t][1] * ilo);
            float2 v1 = make_float2(oc[t][2] * ihi, oc[t][3] * ihi);
            *(float2*)&od[(om0 + r) * Dp + e]     = v0;
            *(float2*)&od[(om0 + 8 + r) * Dp + e] = v1;
        }
    }
}

// ---------------------------------------------------------------------------
extern "C" void kernel_launch(void* const* d_in, const int* in_sizes, int n_in,
                              void* d_out, int out_size) {
    const float* q = (const float*)d_in[0];
    const float* k = (const float*)d_in[1];
    const float* v = (const float*)d_in[2];
    const float* p = (const float*)d_in[3];
    float* out = (float*)d_out;

    const size_t smemA = (size_t)(2 * Fp * PT_S + 2 * CHUNK * XS_S + CHUNK * VT_S + Fp * KPT_S) * 2
                         + 128 * 4;                                    // 138752 B
    const size_t smemB = (size_t)(2 * Fp * PT_S + 2 * CHUNK * XS_S + CHUNK * QP_S + 2 * CHUNK * KVT_S) * 2
                         + (Fp + 128 + 64) * 4;                        // 195328 B

    cudaFuncSetAttribute(kside_kernel, cudaFuncAttributeMaxDynamicSharedMemorySize, (int)smemA);
    cudaFuncSetAttribute(qside_kernel, cudaFuncAttributeMaxDynamicSharedMemorySize, (int)smemB);

    {
        int total = BHp * Fp * Dp;
        zero_scratch<<<(total + 255) / 256, 256>>>();
    }
    dim3 grid(GROUPS, BHp);
    kside_kernel<<<grid, 256, smemA>>>(k, v, p);
    qside_kernel<<<grid, 256, smemB>>>(q, p, out);
}